// round 13
// baseline (speedup 1.0000x reference)
#include <cuda_runtime.h>
#include <cuda_fp16.h>
#include <math.h>
#include <stdint.h>

#define SEQ   2048
#define EMB   512
#define HEADS 8
#define HDIM  64
#define BATCH 2
#define MTOT  (BATCH * SEQ)   // 4096
#define CHUNK 64
#define NCH   (SEQ / CHUNK)   // 32
#define NBH   (BATCH * HEADS) // 16

// ---------------- scratch (static device globals; no allocation) ----------------
__device__ float g_Q [MTOT * EMB];
__device__ float g_K [MTOT * EMB];
__device__ float g_V [MTOT * EMB];
__device__ float g_G [MTOT * EMB];
__device__ float g_A [NBH * NCH * HDIM * HDIM];
__device__ float g_S [NBH * NCH * HDIM * HDIM];
__device__ float g_sin[SEQ * 32];
__device__ float g_cos[SEQ * 32];
__device__ float g_hc [HEADS * 4];
__device__ float g_dk [HEADS * CHUNK];   // gamma^(CHUNK - s), fp64-accurate
// fp16, k-permuted operand copies (pairs (k,k+8) adjacent per 16-k group)
__device__ __half g_CXq[MTOT * EMB];
__device__ __half g_CXk[MTOT * EMB];
__device__ __half g_CXv[MTOT * EMB];
__device__ __half g_CX2[MTOT * EMB];
__device__ __half g_CW [5 * EMB * EMB];

// ---------------- setup: rotary tables + per-head constants (fp64 once) ----------------
__global__ void setup_kernel() {
    int idx = blockIdx.x * blockDim.x + threadIdx.x;
    if (idx < HEADS) {
        const double l0 = log(1.0 / 32.0), l1 = log(1.0 / 512.0);
        double gd = 1.0 - exp(l0 + (double)idx * (l1 - l0) / 7.0);
        g_hc[idx*4 + 0] = (float)gd;
        g_hc[idx*4 + 1] = (float)log(gd);
        g_hc[idx*4 + 2] = (float)pow(gd, (double)CHUNK);
        g_hc[idx*4 + 3] = (float)pow(gd, (double)(8 * CHUNK));
    }
    if (idx < HEADS * CHUNK) {
        int h = idx >> 6;
        int s = idx & 63;
        const double l0 = log(1.0 / 32.0), l1 = log(1.0 / 512.0);
        double gd = 1.0 - exp(l0 + (double)h * (l1 - l0) / 7.0);
        g_dk[idx] = (float)pow(gd, (double)(CHUNK - s));
    }
    if (idx >= SEQ * 32) return;
    int n = idx >> 5;
    int i = idx & 31;
    double t     = (double)i / 31.0;
    double theta = pow(10000.0, -t);
    double ang   = (double)n * theta;
    g_sin[idx] = (float)sin(ang);
    g_cos[idx] = (float)cos(ang);
}

// ---------------- operand convert+permute pre-pass (float -> permuted fp16) ----------------
// Row layout (512 halves): 16 k-tiles of 32 halves. Each k-tile = two 16-k
// groups of 8 words (half2). Word j (k pair 2j) goes to position
// j<4 ? 2j : 2(j-4)+1, so a uint2 at position 2*lc yields k pairs (2lc, 2lc+8).
__device__ __forceinline__ void cvt_rows_h(const float* __restrict__ src,
                                           uint32_t* __restrict__ dst,
                                           int rows, int w)
{
    int row = w >> 8;              // 256 words per row
    if (row >= rows) return;
    int wk    = w & 255;
    int ktile = wk >> 4;
    int pos   = wk & 15;
    int g16   = pos >> 3;
    int q     = pos & 7;
    int j     = (q & 1) ? (q >> 1) + 4 : (q >> 1);
    int k     = ktile * 32 + g16 * 16 + 2 * j;
    const float* s = src + (size_t)row * EMB + k;
    __half2 h = __floats2half2_rn(s[0], s[1]);
    dst[(size_t)row * 256 + wk] = *(uint32_t*)&h;
}

__global__ void __launch_bounds__(256) cvt_inputs_kernel(
    const float* __restrict__ q, const float* __restrict__ k,
    const float* __restrict__ v,
    const float* __restrict__ Wq, const float* __restrict__ Wk,
    const float* __restrict__ Wv, const float* __restrict__ Wg,
    const float* __restrict__ Wo)
{
    int w   = blockIdx.x * 256 + threadIdx.x;
    int job = blockIdx.y;
    switch (job) {
        case 0: cvt_rows_h(q,  (uint32_t*)g_CXq, MTOT, w); break;
        case 1: cvt_rows_h(k,  (uint32_t*)g_CXk, MTOT, w); break;
        case 2: cvt_rows_h(v,  (uint32_t*)g_CXv, MTOT, w); break;
        case 3: cvt_rows_h(Wq, (uint32_t*)(g_CW + 0*EMB*EMB), EMB, w); break;
        case 4: cvt_rows_h(Wk, (uint32_t*)(g_CW + 1*EMB*EMB), EMB, w); break;
        case 5: cvt_rows_h(Wv, (uint32_t*)(g_CW + 2*EMB*EMB), EMB, w); break;
        case 6: cvt_rows_h(Wg, (uint32_t*)(g_CW + 3*EMB*EMB), EMB, w); break;
        default: cvt_rows_h(Wo, (uint32_t*)(g_CW + 4*EMB*EMB), EMB, w); break;
    }
}

// ================= fp16 tensor-core GEMM (3-stage cp.async ring, 2 CTAs/SM) =================
// C[M,512] = X[M,512] @ W[512,512]^T + b, fused epilogue.
// BM x 128, BK=32; 256 threads = 8 warps (2m x 4n), warp tile (BM/2) x 32.
// m16n8k16 f16 mma, fp32 accumulate. Smem row = 16 data words, stride 24.

__device__ __forceinline__ void cp16(uint32_t dst, const void* src) {
    asm volatile("cp.async.cg.shared.global [%0], [%1], 16;" :: "r"(dst), "l"(src));
}

__device__ __forceinline__ void mma_f16(float d[4],
    uint32_t a0, uint32_t a1, uint32_t a2, uint32_t a3,
    uint32_t b0, uint32_t b1)
{
    asm volatile(
        "mma.sync.aligned.m16n8k16.row.col.f32.f16.f16.f32 "
        "{%0,%1,%2,%3}, {%4,%5,%6,%7}, {%8,%9}, {%0,%1,%2,%3};"
        : "+f"(d[0]), "+f"(d[1]), "+f"(d[2]), "+f"(d[3])
        : "r"(a0), "r"(a1), "r"(a2), "r"(a3), "r"(b0), "r"(b1));
}

__device__ __forceinline__ void epi_pair(float& v0, float& v1, int row, int col,
                                         const float* __restrict__ bias, int mode)
{
    v0 += bias[col];
    v1 += bias[col + 1];
    if (mode == 1 || mode == 2) {
        int n = row & (SEQ - 1);
        int d = col & 63;
        float s = g_sin[n*32 + (d >> 1)];
        float c = g_cos[n*32 + (d >> 1)];
        float e = v0, o = v1;
        v0 = e*c - o*s;
        v1 = o*c + e*s;
        if (mode == 2) { v0 *= 0.125f; v1 *= 0.125f; }
    } else if (mode == 3) {
        v0 = v0 / (1.f + expf(-v0));
        v1 = v1 / (1.f + expf(-v1));
    }
}

template<int BM>
__device__ __forceinline__ void gemm_tc(
    const __half* __restrict__ X, const __half* __restrict__ W,
    const float* __restrict__ bias, float* __restrict__ C, int mode)
{
    extern __shared__ uint32_t sm[];
    constexpr int SW  = 24;              // smem row stride (words)
    constexpr int MI  = BM / 32;         // warp m-subtiles (16 rows each)
    constexpr int ASW = BM * SW;         // A words per stage
    constexpr int STW = (BM + 128) * SW; // words per stage

    const int tid  = threadIdx.x;
    const int lane = tid & 31;
    const int warp = tid >> 5;
    const int wm   = (warp >> 2) * (BM / 2);
    const int wn   = (warp & 3) * 32;
    const int lr   = lane >> 2;
    const int lc   = lane & 3;
    const int m0   = blockIdx.y * BM;
    const int n0   = blockIdx.x * 128;

    // loader: rA = tid>>2 (0..63), ch = tid&3 (16B chunk)
    const int rA = tid >> 2;
    const int ch = tid & 3;
    const __half* Xp = X + (size_t)(m0 + rA) * EMB + ch * 8;
    const __half* Wp = W + (size_t)(n0 + rA) * EMB + ch * 8;

    const uint32_t smbase = (uint32_t)__cvta_generic_to_shared(sm);
    const uint32_t doff   = ((uint32_t)(rA * SW) + ch * 4) * 4;   // bytes

    float d[MI][4][4];
    #pragma unroll
    for (int mi = 0; mi < MI; mi++)
        #pragma unroll
        for (int ni = 0; ni < 4; ni++)
            #pragma unroll
            for (int e = 0; e < 4; e++) d[mi][ni][e] = 0.f;

    auto issue = [&](int kt) {
        uint32_t As = smbase + (uint32_t)(kt % 3) * STW * 4;
        uint32_t Bs = As + ASW * 4;
        int kh = kt * 32;                 // k offset in halves
        cp16(As + doff, Xp + kh);
        if (BM == 128)
            cp16(As + doff + 64*SW*4, Xp + kh + (size_t)64 * EMB);
        cp16(Bs + doff,           Wp + kh);
        cp16(Bs + doff + 64*SW*4, Wp + kh + (size_t)64 * EMB);
        asm volatile("cp.async.commit_group;" ::: "memory");
    };

    issue(0);
    issue(1);

    for (int kt = 0; kt < 16; kt++) {
        if (kt < 15) asm volatile("cp.async.wait_group 1;" ::: "memory");
        else         asm volatile("cp.async.wait_group 0;" ::: "memory");
        __syncthreads();

        const uint32_t* As = sm + (kt % 3) * STW;
        const uint32_t* Bs = As + ASW;
        #pragma unroll
        for (int ks = 0; ks < 2; ks++) {
            const int kcol = 8*ks + 2*lc;
            uint2 a_lo[MI], a_hi[MI], bf[4];
            #pragma unroll
            for (int mi = 0; mi < MI; mi++) {
                a_lo[mi] = *(const uint2*)&As[(wm + mi*16 + lr)     * SW + kcol];
                a_hi[mi] = *(const uint2*)&As[(wm + mi*16 + 8 + lr) * SW + kcol];
            }
            #pragma unroll
            for (int ni = 0; ni < 4; ni++)
                bf[ni] = *(const uint2*)&Bs[(wn + ni*8 + lr) * SW + kcol];
            #pragma unroll
            for (int mi = 0; mi < MI; mi++)
                #pragma unroll
                for (int ni = 0; ni < 4; ni++)
                    mma_f16(d[mi][ni], a_lo[mi].x, a_hi[mi].x, a_lo[mi].y, a_hi[mi].y,
                            bf[ni].x, bf[ni].y);
        }
        // write buffer (kt+2)%3 == (kt-1)%3: readers passed this iteration's sync.
        if (kt < 14) issue(kt + 2);
    }

    #pragma unroll
    for (int mi = 0; mi < MI; mi++) {
        int row0 = m0 + wm + mi*16 + lr;
        #pragma unroll
        for (int ni = 0; ni < 4; ni++) {
            int col = n0 + wn + ni*8 + 2*lc;
            float v0 = d[mi][ni][0], v1 = d[mi][ni][1];
            epi_pair(v0, v1, row0, col, bias, mode);
            *(float2*)&C[(size_t)row0 * EMB + col] = make_float2(v0, v1);
            float v2 = d[mi][ni][2], v3 = d[mi][ni][3];
            epi_pair(v2, v3, row0 + 8, col, bias, mode);
            *(float2*)&C[(size_t)(row0 + 8) * EMB + col] = make_float2(v2, v3);
        }
    }
}

__global__ void __launch_bounds__(256) proj_kernel(
    const float* __restrict__ bq, const float* __restrict__ bk,
    const float* __restrict__ bv, const float* __restrict__ bg)
{
    int job = blockIdx.z;
    const __half* X; const __half* W; const float* B; float* O; int mode;
    if      (job == 0) { X = g_CXq; W = g_CW + 0*EMB*EMB; B = bq; O = g_Q; mode = 1; }
    else if (job == 1) { X = g_CXk; W = g_CW + 1*EMB*EMB; B = bk; O = g_K; mode = 2; }
    else if (job == 2) { X = g_CXv; W = g_CW + 2*EMB*EMB; B = bv; O = g_V; mode = 0; }
    else               { X = g_CXq; W = g_CW + 3*EMB*EMB; B = bg; O = g_G; mode = 3; }
    gemm_tc<128>(X, W, B, O, mode);
}

__global__ void __launch_bounds__(256) out_kernel(
    const float* __restrict__ bo, float* __restrict__ out)
{
    gemm_tc<64>(g_CX2, g_CW + 4*EMB*EMB, bo, out, 0);
}

// ================= chunkwise retention =================
// R1: per-chunk A = (K * gamma^(C-j))^T V   [64 x 64]
__global__ void __launch_bounds__(256) chunk_kv_kernel()
{
    __shared__ float Ks[CHUNK * HDIM];
    __shared__ float Vs[CHUNK * HDIM];

    const int tid = threadIdx.x;
    const int tx  = tid & 15;
    const int ty  = tid >> 4;
    const int c   = blockIdx.x;
    const int h   = blockIdx.y;
    const int b   = blockIdx.z;
    const int rowbase = b * SEQ + c * CHUNK;
    const int coff    = h * HDIM;

    for (int f = tid; f < CHUNK * 16; f += 256) {
        int s  = f >> 4;
        int d4 = f & 15;
        size_t gidx = (size_t)(rowbase + s) * EMB + coff + d4*4;
        float sc = g_dk[h*CHUNK + s];
        float4 kv = *(const float4*)&g_K[gidx];
        kv.x *= sc; kv.y *= sc; kv.z *= sc; kv.w *= sc;
        *(float4*)&Ks[s*HDIM + d4*4] = kv;
        *(float4*)&Vs[s*HDIM + d4*4] = *(const float4*)&g_V[gidx];
    }
    __syncthreads();

    float acc[4][4];
    #pragma unroll
    for (int i = 0; i < 4; i++)
        #pragma unroll
        for (int j = 0; j < 4; j++) acc[i][j] = 0.f;

    #pragma unroll 8
    for (int s = 0; s < CHUNK; s++) {
        float4 a = *(const float4*)&Ks[s*HDIM + ty*4];
        float4 bb = *(const float4*)&Vs[s*HDIM + tx*4];
        float av[4] = {a.x, a.y, a.z, a.w};
        float bv[4] = {bb.x, bb.y, bb.z, bb.w};
        #pragma unroll
        for (int i = 0; i < 4; i++)
            #pragma unroll
            for (int j = 0; j < 4; j++)
                acc[i][j] = fmaf(av[i], bv[j], acc[i][j]);
    }

    float* Ap = g_A + (size_t)(((b*HEADS + h)*NCH + c) * HDIM * HDIM);
    #pragma unroll
    for (int i = 0; i < 4; i++)
        *(float4*)&Ap[(ty*4+i)*HDIM + tx*4] =
            make_float4(acc[i][0], acc[i][1], acc[i][2], acc[i][3]);
}

// R2: blocked parallel scan over chunks.
__global__ void __launch_bounds__(256) state_scan_kernel()
{
    __shared__ float Ts[4][64];

    const int tid  = threadIdx.x;
    const int e_lo = tid & 63;
    const int tq   = tid >> 6;
    const int bh   = blockIdx.x;
    const int eseg = blockIdx.y;
    const int e    = eseg * 64 + e_lo;
    const int h    = bh & (HEADS - 1);

    const float gc  = g_hc[h*4 + 2];
    const float gc8 = g_hc[h*4 + 3];

    const size_t base = (size_t)bh * NCH * HDIM * HDIM + e;
    const size_t toff = (size_t)(tq * 8) * HDIM * HDIM;

    float a[8];
    #pragma unroll
    for (int i = 0; i < 8; i++)
        a[i] = g_A[base + toff + (size_t)i * HDIM * HDIM];

    float p[8];
    float s = 0.f;
    #pragma unroll
    for (int i = 0; i < 8; i++) { p[i] = s; s = gc * s + a[i]; }
    Ts[tq][e_lo] = s;
    __syncthreads();

    float cr = 0.f;
    if (tq >= 1) cr = Ts[0][e_lo];
    if (tq >= 2) cr = gc8 * cr + Ts[1][e_lo];
    if (tq >= 3) cr = gc8 * cr + Ts[2][e_lo];

    float gpow = 1.f;
    #pragma unroll
    for (int i = 0; i < 8; i++) {
        g_S[base + toff + (size_t)i * HDIM * HDIM] = fmaf(gpow, cr, p[i]);
        gpow *= gc;
    }
}

// R3: intra-chunk + cross term via state, fused GroupNorm*gate.
// Epilogue writes fp16, k-permuted output directly to g_CX2.
__global__ void __launch_bounds__(256) retention_kernel()
{
    __shared__ float QsT[HDIM * CHUNK];
    __shared__ float KsT[HDIM * CHUNK];
    __shared__ float Vs [CHUNK * HDIM];
    __shared__ float Ss [HDIM * HDIM];

    const int tid = threadIdx.x;
    const int tx  = tid & 15;
    const int ty  = tid >> 4;
    const int c   = blockIdx.x;
    const int h   = blockIdx.y;
    const int b   = blockIdx.z;
    const int rowbase = b * SEQ + c * CHUNK;
    const int coff    = h * HDIM;

    const float gamma = g_hc[h*4 + 0];
    const float lg    = g_hc[h*4 + 1];
    float gi[4], gjv[4];
    gi[0]  = 1.f; gi[1] = gamma; gi[2] = gamma*gamma; gi[3] = gi[2]*gamma;
    float ginv = 1.f / gamma;
    gjv[0] = 1.f; gjv[1] = ginv; gjv[2] = ginv*ginv;  gjv[3] = gjv[2]*ginv;

    const float* Sp = g_S + (size_t)(((b*HEADS + h)*NCH + c) * HDIM * HDIM);
    for (int f = tid; f < CHUNK * 16; f += 256) {
        int s  = f & 63;
        int d4 = f >> 6;
        size_t gidx = (size_t)(rowbase + s) * EMB + coff + d4*4;
        float4 qv = *(const float4*)&g_Q[gidx];
        QsT[(d4*4+0)*CHUNK + s] = qv.x;
        QsT[(d4*4+1)*CHUNK + s] = qv.y;
        QsT[(d4*4+2)*CHUNK + s] = qv.z;
        QsT[(d4*4+3)*CHUNK + s] = qv.w;
        float4 kv = *(const float4*)&g_K[gidx];
        KsT[(d4*4+0)*CHUNK + s] = kv.x;
        KsT[(d4*4+1)*CHUNK + s] = kv.y;
        KsT[(d4*4+2)*CHUNK + s] = kv.z;
        KsT[(d4*4+3)*CHUNK + s] = kv.w;
        *(float4*)&Vs[s*HDIM + d4*4] = *(const float4*)&g_V[gidx];
        *(float4*)&Ss[f*4] = *(const float4*)&Sp[f*4];
    }
    __syncthreads();

    float sacc[4][4];
    #pragma unroll
    for (int i = 0; i < 4; i++)
        #pragma unroll
        for (int j = 0; j < 4; j++) sacc[i][j] = 0.f;
    #pragma unroll 8
    for (int d = 0; d < HDIM; d++) {
        float4 a  = *(const float4*)&QsT[d*CHUNK + ty*4];
        float4 bb = *(const float4*)&KsT[d*CHUNK + tx*4];
        float av[4] = {a.x, a.y, a.z, a.w};
        float bv[4] = {bb.x, bb.y, bb.z, bb.w};
        #pragma unroll
        for (int i = 0; i < 4; i++)
            #pragma unroll
            for (int j = 0; j < 4; j++)
                sacc[i][j] = fmaf(av[i], bv[j], sacc[i][j]);
    }
    {
        float d0 = expf(lg * (float)(ty*4 - tx*4));
        #pragma unroll
        for (int i = 0; i < 4; i++) {
            int n = ty*4 + i;
            #pragma unroll
            for (int j = 0; j < 4; j++) {
                int s = tx*4 + j;
                sacc[i][j] = (s <= n) ? sacc[i][j] * d0 * gi[i] * gjv[j] : 0.f;
            }
        }
    }
    __syncthreads();
    #pragma unroll
    for (int j = 0; j < 4; j++)
        *(float4*)&KsT[(tx*4+j)*CHUNK + ty*4] =
            make_float4(sacc[0][j], sacc[1][j], sacc[2][j], sacc[3][j]);
    __syncthreads();

    float oacc[4][4];
    #pragma unroll
    for (int i = 0; i < 4; i++)
        #pragma unroll
        for (int j = 0; j < 4; j++) oacc[i][j] = 0.f;
    #pragma unroll 8
    for (int s = 0; s < CHUNK; s++) {
        float4 a  = *(const float4*)&KsT[s*CHUNK + ty*4];
        float4 bb = *(const float4*)&Vs[s*HDIM + tx*4];
        float av[4] = {a.x, a.y, a.z, a.w};
        float bv[4] = {bb.x, bb.y, bb.z, bb.w};
        #pragma unroll
        for (int i = 0; i < 4; i++)
            #pragma unroll
            for (int j = 0; j < 4; j++)
                oacc[i][j] = fmaf(av[i], bv[j], oacc[i][j]);
    }

    {
        float cacc[4][4];
        #pragma unroll
        for (int i = 0; i < 4; i++)
            #pragma unroll
            for (int j = 0; j < 4; j++) cacc[i][j] = 0.f;
        #pragma unroll 8
        for (int d = 0; d < HDIM; d++) {
            float4 a  = *(const float4*)&QsT[d*CHUNK + ty*4];
            float4 bb = *(const float4*)&Ss[d*HDIM + tx*4];
            float av[4] = {a.x, a.y, a.z, a.w};
            float bv[4] = {bb.x, bb.y, bb.z, bb.w};
            #pragma unroll
            for (int i = 0; i < 4; i++)
                #pragma unroll
                for (int j = 0; j < 4; j++)
                    cacc[i][j] = fmaf(av[i], bv[j], cacc[i][j]);
        }
        #pragma unroll
        for (int i = 0; i < 4; i++) {
            float gq = expf(lg * (float)(ty*4 + i));
            #pragma unroll
            for (int j = 0; j < 4; j++)
                oacc[i][j] = fmaf(gq, cacc[i][j], oacc[i][j]);
        }
    }

    __syncthreads();
    #pragma unroll
    for (int i = 0; i < 4; i++)
        *(float4*)&KsT[(ty*4+i)*HDIM + tx*4] =
            make_float4(oacc[i][0], oacc[i][1], oacc[i][2], oacc[i][3]);
    __syncthreads();

    const int r = tid >> 2;
    const int p = tid & 3;
    float vals[16];
    float lsum = 0.f;
    #pragma unroll
    for (int j = 0; j < 16; j++) {
        vals[j] = KsT[r*HDIM + p*16 + j];
        lsum += vals[j];
    }
    lsum += __shfl_xor_sync(0xffffffffu, lsum, 1);
    lsum += __shfl_xor_sync(0xffffffffu, lsum, 2);
    float mean = lsum * (1.f / 64.f);
    float lsq = 0.f;
    #pragma unroll
    for (int j = 0; j < 16; j++) {
        float dd = vals[j] - mean;
        lsq += dd * dd;
    }
    lsq += __shfl_xor_sync(0xffffffffu, lsq, 1);
    lsq += __shfl_xor_sync(0xffffffffu, lsq, 2);
    float rstd = rsqrtf(lsq * (1.f / 64.f) + 1e-6f);

    const int n = c * CHUNK + r;
    const size_t rowoff = (size_t)(b * SEQ + n) * EMB;
    #pragma unroll
    for (int j = 0; j < 16; j++) {
        int col = coff + p*16 + j;
        float gte = g_G[rowoff + col];
        float v = (vals[j] - mean) * rstd * gte;
        // permuted fp16 store (same mapping as cvt_rows_h)
        int ktile = col >> 5;
        int k5    = col & 31;
        int g16   = k5 >> 4;
        int kk    = k5 & 15;
        int jw    = kk >> 1;
        int e     = kk & 1;
        int permw = g16*8 + ((jw < 4) ? 2*jw : 2*(jw-4)+1);
        g_CX2[rowoff + ktile*32 + permw*2 + e] = __float2half_rn(v);
    }
}

// ---------------- launch ----------------
extern "C" void kernel_launch(void* const* d_in, const int* in_sizes, int n_in,
                              void* d_out, int out_size)
{
    const float* query = (const float*)d_in[0];
    const float* kk    = (const float*)d_in[1];
    const float* vv    = (const float*)d_in[2];
    const float* Wq    = (const float*)d_in[3];
    const float* bq    = (const float*)d_in[4];
    const float* Wk    = (const float*)d_in[5];
    const float* bk    = (const float*)d_in[6];
    const float* Wv    = (const float*)d_in[7];
    const float* bv    = (const float*)d_in[8];
    const float* Wg    = (const float*)d_in[9];
    const float* bg    = (const float*)d_in[10];
    const float* Wo    = (const float*)d_in[11];
    const float* bo    = (const float*)d_in[12];
    float* out = (float*)d_out;

    const int SMEM_PROJ = 3 * (128 + 128) * 24 * 4;   // 73728 B -> 2 CTAs/SM
    const int SMEM_OUT  = 3 * ( 64 + 128) * 24 * 4;   // 55296 B -> 2 CTAs/SM
    cudaFuncSetAttribute(proj_kernel, cudaFuncAttributeMaxDynamicSharedMemorySize, SMEM_PROJ);
    cudaFuncSetAttribute(out_kernel,  cudaFuncAttributeMaxDynamicSharedMemorySize, SMEM_OUT);

    setup_kernel<<<(SEQ*32 + 255) / 256, 256>>>();

    dim3 cg(MTOT * 256 / 256, 8);          // words per tensor / 256 threads
    cvt_inputs_kernel<<<cg, 256>>>(query, kk, vv, Wq, Wk, Wv, Wg, Wo);

    dim3 pg(4, 32, 4);
    proj_kernel<<<pg, 256, SMEM_PROJ>>>(bq, bk, bv, bg);

    dim3 ag(NCH, HEADS, BATCH);
    chunk_kv_kernel<<<ag, 256>>>();

    dim3 sg(NBH, 64);
    state_scan_kernel<<<sg, 256>>>();

    dim3 rg(NCH, HEADS, BATCH);
    retention_kernel<<<rg, 256>>>();

    dim3 og(4, 64, 1);                     // BM=64 -> 256 blocks (full chip)
    out_kernel<<<og, 256, SMEM_OUT>>>(bo, out);
}

// round 14
// speedup vs baseline: 1.0074x; 1.0074x over previous
#include <cuda_runtime.h>
#include <cuda_fp16.h>
#include <math.h>
#include <stdint.h>

#define SEQ   2048
#define EMB   512
#define HEADS 8
#define HDIM  64
#define BATCH 2
#define MTOT  (BATCH * SEQ)   // 4096
#define CHUNK 64
#define NCH   (SEQ / CHUNK)   // 32
#define NBH   (BATCH * HEADS) // 16

// ---------------- scratch (static device globals; no allocation) ----------------
__device__ float g_Q [MTOT * EMB];
__device__ float g_K [MTOT * EMB];
__device__ float g_V [MTOT * EMB];
__device__ float g_G [MTOT * EMB];
__device__ float g_A [NBH * NCH * HDIM * HDIM];
__device__ float g_S [NBH * NCH * HDIM * HDIM];
__device__ float g_sin[SEQ * 32];
__device__ float g_cos[SEQ * 32];
__device__ float g_hc [HEADS * 4];
__device__ float g_dk [HEADS * CHUNK];   // gamma^(CHUNK - s), fp64-accurate
// fp16, k-permuted operand copies (pairs (k,k+8) adjacent per 16-k group)
__device__ __half g_CXq[MTOT * EMB];
__device__ __half g_CXk[MTOT * EMB];
__device__ __half g_CXv[MTOT * EMB];
__device__ __half g_CX2[MTOT * EMB];
__device__ __half g_CW [5 * EMB * EMB];

// ---------------- setup: rotary tables + per-head constants (fp64 once) ----------------
__global__ void setup_kernel() {
    int idx = blockIdx.x * blockDim.x + threadIdx.x;
    if (idx < HEADS) {
        const double l0 = log(1.0 / 32.0), l1 = log(1.0 / 512.0);
        double gd = 1.0 - exp(l0 + (double)idx * (l1 - l0) / 7.0);
        g_hc[idx*4 + 0] = (float)gd;
        g_hc[idx*4 + 1] = (float)log(gd);
        g_hc[idx*4 + 2] = (float)pow(gd, (double)CHUNK);
        g_hc[idx*4 + 3] = (float)pow(gd, (double)(8 * CHUNK));
    }
    if (idx < HEADS * CHUNK) {
        int h = idx >> 6;
        int s = idx & 63;
        const double l0 = log(1.0 / 32.0), l1 = log(1.0 / 512.0);
        double gd = 1.0 - exp(l0 + (double)h * (l1 - l0) / 7.0);
        g_dk[idx] = (float)pow(gd, (double)(CHUNK - s));
    }
    if (idx >= SEQ * 32) return;
    int n = idx >> 5;
    int i = idx & 31;
    double t     = (double)i / 31.0;
    double theta = pow(10000.0, -t);
    double ang   = (double)n * theta;
    g_sin[idx] = (float)sin(ang);
    g_cos[idx] = (float)cos(ang);
}

// ---------------- operand convert+permute pre-pass (float -> permuted fp16) ----------------
__device__ __forceinline__ void cvt_rows_h(const float* __restrict__ src,
                                           uint32_t* __restrict__ dst,
                                           int rows, int w)
{
    int row = w >> 8;              // 256 words per row
    if (row >= rows) return;
    int wk    = w & 255;
    int ktile = wk >> 4;
    int pos   = wk & 15;
    int g16   = pos >> 3;
    int q     = pos & 7;
    int j     = (q & 1) ? (q >> 1) + 4 : (q >> 1);
    int k     = ktile * 32 + g16 * 16 + 2 * j;
    const float* s = src + (size_t)row * EMB + k;
    __half2 h = __floats2half2_rn(s[0], s[1]);
    dst[(size_t)row * 256 + wk] = *(uint32_t*)&h;
}

__global__ void __launch_bounds__(256) cvt_inputs_kernel(
    const float* __restrict__ q, const float* __restrict__ k,
    const float* __restrict__ v,
    const float* __restrict__ Wq, const float* __restrict__ Wk,
    const float* __restrict__ Wv, const float* __restrict__ Wg,
    const float* __restrict__ Wo)
{
    int w   = blockIdx.x * 256 + threadIdx.x;
    int job = blockIdx.y;
    switch (job) {
        case 0: cvt_rows_h(q,  (uint32_t*)g_CXq, MTOT, w); break;
        case 1: cvt_rows_h(k,  (uint32_t*)g_CXk, MTOT, w); break;
        case 2: cvt_rows_h(v,  (uint32_t*)g_CXv, MTOT, w); break;
        case 3: cvt_rows_h(Wq, (uint32_t*)(g_CW + 0*EMB*EMB), EMB, w); break;
        case 4: cvt_rows_h(Wk, (uint32_t*)(g_CW + 1*EMB*EMB), EMB, w); break;
        case 5: cvt_rows_h(Wv, (uint32_t*)(g_CW + 2*EMB*EMB), EMB, w); break;
        case 6: cvt_rows_h(Wg, (uint32_t*)(g_CW + 3*EMB*EMB), EMB, w); break;
        default: cvt_rows_h(Wo, (uint32_t*)(g_CW + 4*EMB*EMB), EMB, w); break;
    }
}

// ================= fp16 tensor-core GEMM (3-stage cp.async ring, 2 CTAs/SM) =================
// C[M,512] = X[M,512] @ W[512,512]^T + b, fused epilogue.
// BM=BN=128, BK=32; 256 threads = 8 warps (2m x 4n), warp tile 64x32.
// m16n8k16 f16 mma, fp32 accumulate. Smem row = 16 data words, stride 24.
// Stage = 24KB; 3 stages = 72KB -> 2 CTAs/SM, ONE __syncthreads per k-tile.

__device__ __forceinline__ void cp16(uint32_t dst, const void* src) {
    asm volatile("cp.async.cg.shared.global [%0], [%1], 16;" :: "r"(dst), "l"(src));
}

__device__ __forceinline__ void mma_f16(float d[4],
    uint32_t a0, uint32_t a1, uint32_t a2, uint32_t a3,
    uint32_t b0, uint32_t b1)
{
    asm volatile(
        "mma.sync.aligned.m16n8k16.row.col.f32.f16.f16.f32 "
        "{%0,%1,%2,%3}, {%4,%5,%6,%7}, {%8,%9}, {%0,%1,%2,%3};"
        : "+f"(d[0]), "+f"(d[1]), "+f"(d[2]), "+f"(d[3])
        : "r"(a0), "r"(a1), "r"(a2), "r"(a3), "r"(b0), "r"(b1));
}

__device__ __forceinline__ void epi_pair(float& v0, float& v1, int row, int col,
                                         const float* __restrict__ bias, int mode)
{
    v0 += bias[col];
    v1 += bias[col + 1];
    if (mode == 1 || mode == 2) {
        int n = row & (SEQ - 1);
        int d = col & 63;
        float s = g_sin[n*32 + (d >> 1)];
        float c = g_cos[n*32 + (d >> 1)];
        float e = v0, o = v1;
        v0 = e*c - o*s;
        v1 = o*c + e*s;
        if (mode == 2) { v0 *= 0.125f; v1 *= 0.125f; }
    } else if (mode == 3) {
        v0 = v0 / (1.f + expf(-v0));
        v1 = v1 / (1.f + expf(-v1));
    }
}

__device__ __forceinline__ void gemm_tc(
    const __half* __restrict__ X, const __half* __restrict__ W,
    const float* __restrict__ bias, float* __restrict__ C, int mode)
{
    extern __shared__ uint32_t sm[];
    constexpr int SW  = 24;              // smem row stride (words)
    constexpr int HSW = 128 * SW;        // words per half (A or B)
    constexpr int STW = 2 * HSW;         // words per stage

    const int tid  = threadIdx.x;
    const int lane = tid & 31;
    const int warp = tid >> 5;
    const int wm   = (warp >> 2) * 64;
    const int wn   = (warp & 3) * 32;
    const int lr   = lane >> 2;
    const int lc   = lane & 3;
    const int m0   = blockIdx.y * 128;
    const int n0   = blockIdx.x * 128;

    const int rA = tid >> 2;
    const int ch = tid & 3;
    const __half* Xp = X + (size_t)(m0 + rA) * EMB + ch * 8;
    const __half* Wp = W + (size_t)(n0 + rA) * EMB + ch * 8;

    const uint32_t smbase = (uint32_t)__cvta_generic_to_shared(sm);
    const uint32_t doff   = ((uint32_t)(rA * SW) + ch * 4) * 4;

    float d[4][4][4];
    #pragma unroll
    for (int mi = 0; mi < 4; mi++)
        #pragma unroll
        for (int ni = 0; ni < 4; ni++)
            #pragma unroll
            for (int e = 0; e < 4; e++) d[mi][ni][e] = 0.f;

    auto issue = [&](int kt) {
        uint32_t As = smbase + (uint32_t)(kt % 3) * STW * 4;
        uint32_t Bs = As + HSW * 4;
        int kh = kt * 32;
        cp16(As + doff,           Xp + kh);
        cp16(As + doff + 64*SW*4, Xp + kh + (size_t)64 * EMB);
        cp16(Bs + doff,           Wp + kh);
        cp16(Bs + doff + 64*SW*4, Wp + kh + (size_t)64 * EMB);
        asm volatile("cp.async.commit_group;" ::: "memory");
    };

    issue(0);
    issue(1);

    for (int kt = 0; kt < 16; kt++) {
        if (kt < 15) asm volatile("cp.async.wait_group 1;" ::: "memory");
        else         asm volatile("cp.async.wait_group 0;" ::: "memory");
        __syncthreads();

        const uint32_t* As = sm + (kt % 3) * STW;
        const uint32_t* Bs = As + HSW;
        #pragma unroll
        for (int ks = 0; ks < 2; ks++) {
            const int kcol = 8*ks + 2*lc;
            uint2 a_lo[4], a_hi[4], bf[4];
            #pragma unroll
            for (int mi = 0; mi < 4; mi++) {
                a_lo[mi] = *(const uint2*)&As[(wm + mi*16 + lr)     * SW + kcol];
                a_hi[mi] = *(const uint2*)&As[(wm + mi*16 + 8 + lr) * SW + kcol];
            }
            #pragma unroll
            for (int ni = 0; ni < 4; ni++)
                bf[ni] = *(const uint2*)&Bs[(wn + ni*8 + lr) * SW + kcol];
            #pragma unroll
            for (int mi = 0; mi < 4; mi++)
                #pragma unroll
                for (int ni = 0; ni < 4; ni++)
                    mma_f16(d[mi][ni], a_lo[mi].x, a_hi[mi].x, a_lo[mi].y, a_hi[mi].y,
                            bf[ni].x, bf[ni].y);
        }
        if (kt < 14) issue(kt + 2);
    }

    #pragma unroll
    for (int mi = 0; mi < 4; mi++) {
        int row0 = m0 + wm + mi*16 + lr;
        #pragma unroll
        for (int ni = 0; ni < 4; ni++) {
            int col = n0 + wn + ni*8 + 2*lc;
            float v0 = d[mi][ni][0], v1 = d[mi][ni][1];
            epi_pair(v0, v1, row0, col, bias, mode);
            *(float2*)&C[(size_t)row0 * EMB + col] = make_float2(v0, v1);
            float v2 = d[mi][ni][2], v3 = d[mi][ni][3];
            epi_pair(v2, v3, row0 + 8, col, bias, mode);
            *(float2*)&C[(size_t)(row0 + 8) * EMB + col] = make_float2(v2, v3);
        }
    }
}

__global__ void __launch_bounds__(256) proj_kernel(
    const float* __restrict__ bq, const float* __restrict__ bk,
    const float* __restrict__ bv, const float* __restrict__ bg)
{
    int job = blockIdx.z;
    const __half* X; const __half* W; const float* B; float* O; int mode;
    if      (job == 0) { X = g_CXq; W = g_CW + 0*EMB*EMB; B = bq; O = g_Q; mode = 1; }
    else if (job == 1) { X = g_CXk; W = g_CW + 1*EMB*EMB; B = bk; O = g_K; mode = 2; }
    else if (job == 2) { X = g_CXv; W = g_CW + 2*EMB*EMB; B = bv; O = g_V; mode = 0; }
    else               { X = g_CXq; W = g_CW + 3*EMB*EMB; B = bg; O = g_G; mode = 3; }
    gemm_tc(X, W, B, O, mode);
}

__global__ void __launch_bounds__(256) out_kernel(
    const float* __restrict__ bo, float* __restrict__ out)
{
    gemm_tc(g_CX2, g_CW + 4*EMB*EMB, bo, out, 0);
}

// ================= chunkwise retention =================
// R1: per-chunk A = (K * gamma^(C-j))^T V   [64 x 64]
__global__ void __launch_bounds__(256) chunk_kv_kernel()
{
    __shared__ float Ks[CHUNK * HDIM];
    __shared__ float Vs[CHUNK * HDIM];

    const int tid = threadIdx.x;
    const int tx  = tid & 15;
    const int ty  = tid >> 4;
    const int c   = blockIdx.x;
    const int h   = blockIdx.y;
    const int b   = blockIdx.z;
    const int rowbase = b * SEQ + c * CHUNK;
    const int coff    = h * HDIM;

    for (int f = tid; f < CHUNK * 16; f += 256) {
        int s  = f >> 4;
        int d4 = f & 15;
        size_t gidx = (size_t)(rowbase + s) * EMB + coff + d4*4;
        float sc = g_dk[h*CHUNK + s];
        float4 kv = *(const float4*)&g_K[gidx];
        kv.x *= sc; kv.y *= sc; kv.z *= sc; kv.w *= sc;
        *(float4*)&Ks[s*HDIM + d4*4] = kv;
        *(float4*)&Vs[s*HDIM + d4*4] = *(const float4*)&g_V[gidx];
    }
    __syncthreads();

    float acc[4][4];
    #pragma unroll
    for (int i = 0; i < 4; i++)
        #pragma unroll
        for (int j = 0; j < 4; j++) acc[i][j] = 0.f;

    #pragma unroll 8
    for (int s = 0; s < CHUNK; s++) {
        float4 a = *(const float4*)&Ks[s*HDIM + ty*4];
        float4 bb = *(const float4*)&Vs[s*HDIM + tx*4];
        float av[4] = {a.x, a.y, a.z, a.w};
        float bv[4] = {bb.x, bb.y, bb.z, bb.w};
        #pragma unroll
        for (int i = 0; i < 4; i++)
            #pragma unroll
            for (int j = 0; j < 4; j++)
                acc[i][j] = fmaf(av[i], bv[j], acc[i][j]);
    }

    float* Ap = g_A + (size_t)(((b*HEADS + h)*NCH + c) * HDIM * HDIM);
    #pragma unroll
    for (int i = 0; i < 4; i++)
        *(float4*)&Ap[(ty*4+i)*HDIM + tx*4] =
            make_float4(acc[i][0], acc[i][1], acc[i][2], acc[i][3]);
}

// R2: blocked parallel scan over chunks.
__global__ void __launch_bounds__(256) state_scan_kernel()
{
    __shared__ float Ts[4][64];

    const int tid  = threadIdx.x;
    const int e_lo = tid & 63;
    const int tq   = tid >> 6;
    const int bh   = blockIdx.x;
    const int eseg = blockIdx.y;
    const int e    = eseg * 64 + e_lo;
    const int h    = bh & (HEADS - 1);

    const float gc  = g_hc[h*4 + 2];
    const float gc8 = g_hc[h*4 + 3];

    const size_t base = (size_t)bh * NCH * HDIM * HDIM + e;
    const size_t toff = (size_t)(tq * 8) * HDIM * HDIM;

    float a[8];
    #pragma unroll
    for (int i = 0; i < 8; i++)
        a[i] = g_A[base + toff + (size_t)i * HDIM * HDIM];

    float p[8];
    float s = 0.f;
    #pragma unroll
    for (int i = 0; i < 8; i++) { p[i] = s; s = gc * s + a[i]; }
    Ts[tq][e_lo] = s;
    __syncthreads();

    float cr = 0.f;
    if (tq >= 1) cr = Ts[0][e_lo];
    if (tq >= 2) cr = gc8 * cr + Ts[1][e_lo];
    if (tq >= 3) cr = gc8 * cr + Ts[2][e_lo];

    float gpow = 1.f;
    #pragma unroll
    for (int i = 0; i < 8; i++) {
        g_S[base + toff + (size_t)i * HDIM * HDIM] = fmaf(gpow, cr, p[i]);
        gpow *= gc;
    }
}

// R3: intra-chunk + cross term via state, fused GroupNorm*gate.
// GEMM1 (QK^T) and GEMM3 (Q.S) share one d-loop (QsT fragment reused).
// Epilogue writes fp16, k-permuted output directly to g_CX2.
__global__ void __launch_bounds__(256) retention_kernel()
{
    __shared__ float QsT[HDIM * CHUNK];
    __shared__ float KsT[HDIM * CHUNK];
    __shared__ float Vs [CHUNK * HDIM];
    __shared__ float Ss [HDIM * HDIM];

    const int tid = threadIdx.x;
    const int tx  = tid & 15;
    const int ty  = tid >> 4;
    const int c   = blockIdx.x;
    const int h   = blockIdx.y;
    const int b   = blockIdx.z;
    const int rowbase = b * SEQ + c * CHUNK;
    const int coff    = h * HDIM;

    const float gamma = g_hc[h*4 + 0];
    const float lg    = g_hc[h*4 + 1];
    float gi[4], gjv[4];
    gi[0]  = 1.f; gi[1] = gamma; gi[2] = gamma*gamma; gi[3] = gi[2]*gamma;
    float ginv = 1.f / gamma;
    gjv[0] = 1.f; gjv[1] = ginv; gjv[2] = ginv*ginv;  gjv[3] = gjv[2]*ginv;

    const float* Sp = g_S + (size_t)(((b*HEADS + h)*NCH + c) * HDIM * HDIM);
    for (int f = tid; f < CHUNK * 16; f += 256) {
        int s  = f & 63;
        int d4 = f >> 6;
        size_t gidx = (size_t)(rowbase + s) * EMB + coff + d4*4;
        float4 qv = *(const float4*)&g_Q[gidx];
        QsT[(d4*4+0)*CHUNK + s] = qv.x;
        QsT[(d4*4+1)*CHUNK + s] = qv.y;
        QsT[(d4*4+2)*CHUNK + s] = qv.z;
        QsT[(d4*4+3)*CHUNK + s] = qv.w;
        float4 kv = *(const float4*)&g_K[gidx];
        KsT[(d4*4+0)*CHUNK + s] = kv.x;
        KsT[(d4*4+1)*CHUNK + s] = kv.y;
        KsT[(d4*4+2)*CHUNK + s] = kv.z;
        KsT[(d4*4+3)*CHUNK + s] = kv.w;
        *(float4*)&Vs[s*HDIM + d4*4] = *(const float4*)&g_V[gidx];
        *(float4*)&Ss[f*4] = *(const float4*)&Sp[f*4];
    }
    __syncthreads();

    // fused GEMM1 + GEMM3 over d: sacc = Q K^T tile; cacc = Q S tile
    float sacc[4][4], cacc[4][4];
    #pragma unroll
    for (int i = 0; i < 4; i++)
        #pragma unroll
        for (int j = 0; j < 4; j++) { sacc[i][j] = 0.f; cacc[i][j] = 0.f; }
    #pragma unroll 4
    for (int d = 0; d < HDIM; d++) {
        float4 a  = *(const float4*)&QsT[d*CHUNK + ty*4];
        float4 bb = *(const float4*)&KsT[d*CHUNK + tx*4];
        float4 cc = *(const float4*)&Ss [d*HDIM  + tx*4];
        float av[4] = {a.x, a.y, a.z, a.w};
        float bv[4] = {bb.x, bb.y, bb.z, bb.w};
        float cv[4] = {cc.x, cc.y, cc.z, cc.w};
        #pragma unroll
        for (int i = 0; i < 4; i++)
            #pragma unroll
            for (int j = 0; j < 4; j++) {
                sacc[i][j] = fmaf(av[i], bv[j], sacc[i][j]);
                cacc[i][j] = fmaf(av[i], cv[j], cacc[i][j]);
            }
    }
    {
        float d0 = expf(lg * (float)(ty*4 - tx*4));
        #pragma unroll
        for (int i = 0; i < 4; i++) {
            int n = ty*4 + i;
            #pragma unroll
            for (int j = 0; j < 4; j++) {
                int s = tx*4 + j;
                sacc[i][j] = (s <= n) ? sacc[i][j] * d0 * gi[i] * gjv[j] : 0.f;
            }
        }
    }
    __syncthreads();
    #pragma unroll
    for (int j = 0; j < 4; j++)
        *(float4*)&KsT[(tx*4+j)*CHUNK + ty*4] =
            make_float4(sacc[0][j], sacc[1][j], sacc[2][j], sacc[3][j]);
    __syncthreads();

    // oacc starts from the cross term: gamma^(q) * (Q S)
    float oacc[4][4];
    #pragma unroll
    for (int i = 0; i < 4; i++) {
        float gq = expf(lg * (float)(ty*4 + i));
        #pragma unroll
        for (int j = 0; j < 4; j++) oacc[i][j] = gq * cacc[i][j];
    }
    // GEMM2: O += sum_s S^T[s][q] * Vs[s][d]
    #pragma unroll 8
    for (int s = 0; s < CHUNK; s++) {
        float4 a  = *(const float4*)&KsT[s*CHUNK + ty*4];
        float4 bb = *(const float4*)&Vs[s*HDIM + tx*4];
        float av[4] = {a.x, a.y, a.z, a.w};
        float bv[4] = {bb.x, bb.y, bb.z, bb.w};
        #pragma unroll
        for (int i = 0; i < 4; i++)
            #pragma unroll
            for (int j = 0; j < 4; j++)
                oacc[i][j] = fmaf(av[i], bv[j], oacc[i][j]);
    }

    __syncthreads();
    #pragma unroll
    for (int i = 0; i < 4; i++)
        *(float4*)&KsT[(ty*4+i)*HDIM + tx*4] =
            make_float4(oacc[i][0], oacc[i][1], oacc[i][2], oacc[i][3]);
    __syncthreads();

    const int r = tid >> 2;
    const int p = tid & 3;
    float vals[16];
    float lsum = 0.f;
    #pragma unroll
    for (int j = 0; j < 16; j++) {
        vals[j] = KsT[r*HDIM + p*16 + j];
        lsum += vals[j];
    }
    lsum += __shfl_xor_sync(0xffffffffu, lsum, 1);
    lsum += __shfl_xor_sync(0xffffffffu, lsum, 2);
    float mean = lsum * (1.f / 64.f);
    float lsq = 0.f;
    #pragma unroll
    for (int j = 0; j < 16; j++) {
        float dd = vals[j] - mean;
        lsq += dd * dd;
    }
    lsq += __shfl_xor_sync(0xffffffffu, lsq, 1);
    lsq += __shfl_xor_sync(0xffffffffu, lsq, 2);
    float rstd = rsqrtf(lsq * (1.f / 64.f) + 1e-6f);

    const int n = c * CHUNK + r;
    const size_t rowoff = (size_t)(b * SEQ + n) * EMB;
    #pragma unroll
    for (int j = 0; j < 16; j++) {
        int col = coff + p*16 + j;
        float gte = g_G[rowoff + col];
        float v = (vals[j] - mean) * rstd * gte;
        int ktile = col >> 5;
        int k5    = col & 31;
        int g16   = k5 >> 4;
        int kk    = k5 & 15;
        int jw    = kk >> 1;
        int e     = kk & 1;
        int permw = g16*8 + ((jw < 4) ? 2*jw : 2*(jw-4)+1);
        g_CX2[rowoff + ktile*32 + permw*2 + e] = __float2half_rn(v);
    }
}

// ---------------- launch ----------------
extern "C" void kernel_launch(void* const* d_in, const int* in_sizes, int n_in,
                              void* d_out, int out_size)
{
    const float* query = (const float*)d_in[0];
    const float* kk    = (const float*)d_in[1];
    const float* vv    = (const float*)d_in[2];
    const float* Wq    = (const float*)d_in[3];
    const float* bq    = (const float*)d_in[4];
    const float* Wk    = (const float*)d_in[5];
    const float* bk    = (const float*)d_in[6];
    const float* Wv    = (const float*)d_in[7];
    const float* bv    = (const float*)d_in[8];
    const float* Wg    = (const float*)d_in[9];
    const float* bg    = (const float*)d_in[10];
    const float* Wo    = (const float*)d_in[11];
    const float* bo    = (const float*)d_in[12];
    float* out = (float*)d_out;

    const int SMEM_GEMM = 3 * 2 * 128 * 24 * 4;   // 73728 B -> 2 CTAs/SM
    cudaFuncSetAttribute(proj_kernel, cudaFuncAttributeMaxDynamicSharedMemorySize, SMEM_GEMM);
    cudaFuncSetAttribute(out_kernel,  cudaFuncAttributeMaxDynamicSharedMemorySize, SMEM_GEMM);

    setup_kernel<<<(SEQ*32 + 255) / 256, 256>>>();

    dim3 cg(MTOT * 256 / 256, 8);
    cvt_inputs_kernel<<<cg, 256>>>(query, kk, vv, Wq, Wk, Wv, Wg, Wo);

    dim3 pg(4, 32, 4);
    proj_kernel<<<pg, 256, SMEM_GEMM>>>(bq, bk, bv, bg);

    dim3 ag(NCH, HEADS, BATCH);
    chunk_kv_kernel<<<ag, 256>>>();

    dim3 sg(NBH, 64);
    state_scan_kernel<<<sg, 256>>>();

    dim3 rg(NCH, HEADS, BATCH);
    retention_kernel<<<rg, 256>>>();

    dim3 og(4, 32, 1);
    out_kernel<<<og, 256, SMEM_GEMM>>>(bo, out);
}

// round 15
// speedup vs baseline: 1.1264x; 1.1181x over previous
#include <cuda_runtime.h>
#include <cuda_fp16.h>
#include <math.h>
#include <stdint.h>

#define SEQ   2048
#define EMB   512
#define HEADS 8
#define HDIM  64
#define BATCH 2
#define MTOT  (BATCH * SEQ)   // 4096
#define CHUNK 64
#define NCH   (SEQ / CHUNK)   // 32
#define NBH   (BATCH * HEADS) // 16

// ---------------- scratch (static device globals; no allocation) ----------------
__device__ float g_Q [MTOT * EMB];
__device__ float g_K [MTOT * EMB];
__device__ float g_V [MTOT * EMB];
__device__ float g_G [MTOT * EMB];
__device__ float g_A [NBH * NCH * HDIM * HDIM];
__device__ float g_S [NBH * NCH * HDIM * HDIM];
__device__ float g_sin[SEQ * 32];
__device__ float g_cos[SEQ * 32];
__device__ float g_hc [HEADS * 4];
// fp16, k-permuted operand copies (pairs (k,k+8) adjacent per 16-k group)
__device__ __half g_CXq[MTOT * EMB];
__device__ __half g_CXk[MTOT * EMB];
__device__ __half g_CXv[MTOT * EMB];
__device__ __half g_CX2[MTOT * EMB];
__device__ __half g_CW [5 * EMB * EMB];

// ---------------- operand convert+permute: float -> permuted fp16, 4 words/thread ----------------
// Row layout (512 halves = 256 words): 16 k-tiles of 16 words. Within a k-tile,
// word j (k pair 2j of a 16-k group) sits at position j<4 ? 2j : 2(j-4)+1.
// Inverse (output pos -> source): q = pos&7, j = (q&1) ? (q>>1)+4 : (q>>1).
__device__ __forceinline__ void cvt_rows_h4(const float* __restrict__ src,
                                            uint32_t* __restrict__ dst,
                                            int rows, int idx4)
{
    int row = idx4 >> 6;           // 64 threads per row
    if (row >= rows) return;
    int wk0 = (idx4 & 63) * 4;     // first of 4 consecutive output words
    uint32_t wout[4];
    #pragma unroll
    for (int p = 0; p < 4; p++) {
        int wk    = wk0 + p;
        int ktile = wk >> 4;
        int pos   = wk & 15;
        int g16   = pos >> 3;
        int q     = pos & 7;
        int j     = (q & 1) ? (q >> 1) + 4 : (q >> 1);
        int k     = ktile * 32 + g16 * 16 + 2 * j;
        const float* s = src + (size_t)row * EMB + k;
        __half2 h = __floats2half2_rn(s[0], s[1]);
        wout[p] = *(uint32_t*)&h;
    }
    *(uint4*)&dst[(size_t)row * 256 + wk0] = make_uint4(wout[0], wout[1], wout[2], wout[3]);
}

// job 0 also performs setup (rotary tables + per-head constants, fp64 once)
__global__ void __launch_bounds__(256) cvt_inputs_kernel(
    const float* __restrict__ q, const float* __restrict__ k,
    const float* __restrict__ v,
    const float* __restrict__ Wq, const float* __restrict__ Wk,
    const float* __restrict__ Wv, const float* __restrict__ Wg,
    const float* __restrict__ Wo)
{
    int idx4 = blockIdx.x * 256 + threadIdx.x;
    int job  = blockIdx.y;
    switch (job) {
        case 0: {
            // setup work (independent outputs; ready before proj launch)
            int gid = idx4;
            if (gid < HEADS) {
                const double l0 = log(1.0 / 32.0), l1 = log(1.0 / 512.0);
                double gd = 1.0 - exp(l0 + (double)gid * (l1 - l0) / 7.0);
                g_hc[gid*4 + 0] = (float)gd;
                g_hc[gid*4 + 1] = (float)log(gd);
                g_hc[gid*4 + 2] = (float)pow(gd, (double)CHUNK);
                g_hc[gid*4 + 3] = (float)pow(gd, (double)(8 * CHUNK));
            }
            if (gid < SEQ * 32) {
                int n = gid >> 5;
                int i = gid & 31;
                double t     = (double)i / 31.0;
                double theta = pow(10000.0, -t);
                double ang   = (double)n * theta;
                g_sin[gid] = (float)sin(ang);
                g_cos[gid] = (float)cos(ang);
            }
            cvt_rows_h4(q,  (uint32_t*)g_CXq, MTOT, idx4);
            break;
        }
        case 1: cvt_rows_h4(k,  (uint32_t*)g_CXk, MTOT, idx4); break;
        case 2: cvt_rows_h4(v,  (uint32_t*)g_CXv, MTOT, idx4); break;
        case 3: cvt_rows_h4(Wq, (uint32_t*)(g_CW + 0*EMB*EMB), EMB, idx4); break;
        case 4: cvt_rows_h4(Wk, (uint32_t*)(g_CW + 1*EMB*EMB), EMB, idx4); break;
        case 5: cvt_rows_h4(Wv, (uint32_t*)(g_CW + 2*EMB*EMB), EMB, idx4); break;
        case 6: cvt_rows_h4(Wg, (uint32_t*)(g_CW + 3*EMB*EMB), EMB, idx4); break;
        default: cvt_rows_h4(Wo, (uint32_t*)(g_CW + 4*EMB*EMB), EMB, idx4); break;
    }
}

// ================= fp16 tensor-core GEMM (3-stage cp.async ring, 2 CTAs/SM) =================
// C[M,512] = X[M,512] @ W[512,512]^T + b, fused epilogue.
// BM=BN=128, BK=32; 256 threads = 8 warps (2m x 4n), warp tile 64x32.
// m16n8k16 f16 mma, fp32 accumulate. Smem row = 16 data words, stride 24.
// Stage = 24KB; 3 stages = 72KB -> 2 CTAs/SM, ONE __syncthreads per k-tile.

__device__ __forceinline__ void cp16(uint32_t dst, const void* src) {
    asm volatile("cp.async.cg.shared.global [%0], [%1], 16;" :: "r"(dst), "l"(src));
}

__device__ __forceinline__ void mma_f16(float d[4],
    uint32_t a0, uint32_t a1, uint32_t a2, uint32_t a3,
    uint32_t b0, uint32_t b1)
{
    asm volatile(
        "mma.sync.aligned.m16n8k16.row.col.f32.f16.f16.f32 "
        "{%0,%1,%2,%3}, {%4,%5,%6,%7}, {%8,%9}, {%0,%1,%2,%3};"
        : "+f"(d[0]), "+f"(d[1]), "+f"(d[2]), "+f"(d[3])
        : "r"(a0), "r"(a1), "r"(a2), "r"(a3), "r"(b0), "r"(b1));
}

__device__ __forceinline__ void epi_pair(float& v0, float& v1, int row, int col,
                                         const float* __restrict__ bias, int mode)
{
    v0 += bias[col];
    v1 += bias[col + 1];
    if (mode == 1 || mode == 2) {
        int n = row & (SEQ - 1);
        int d = col & 63;
        float s = g_sin[n*32 + (d >> 1)];
        float c = g_cos[n*32 + (d >> 1)];
        float e = v0, o = v1;
        v0 = e*c - o*s;
        v1 = o*c + e*s;
        if (mode == 2) { v0 *= 0.125f; v1 *= 0.125f; }
    } else if (mode == 3) {
        v0 = v0 / (1.f + expf(-v0));
        v1 = v1 / (1.f + expf(-v1));
    }
}

__device__ __forceinline__ void gemm_tc(
    const __half* __restrict__ X, const __half* __restrict__ W,
    const float* __restrict__ bias, float* __restrict__ C, int mode)
{
    extern __shared__ uint32_t sm[];
    constexpr int SW  = 24;              // smem row stride (words)
    constexpr int HSW = 128 * SW;        // words per half (A or B)
    constexpr int STW = 2 * HSW;         // words per stage

    const int tid  = threadIdx.x;
    const int lane = tid & 31;
    const int warp = tid >> 5;
    const int wm   = (warp >> 2) * 64;
    const int wn   = (warp & 3) * 32;
    const int lr   = lane >> 2;
    const int lc   = lane & 3;
    const int m0   = blockIdx.y * 128;
    const int n0   = blockIdx.x * 128;

    const int rA = tid >> 2;
    const int ch = tid & 3;
    const __half* Xp = X + (size_t)(m0 + rA) * EMB + ch * 8;
    const __half* Wp = W + (size_t)(n0 + rA) * EMB + ch * 8;

    const uint32_t smbase = (uint32_t)__cvta_generic_to_shared(sm);
    const uint32_t doff   = ((uint32_t)(rA * SW) + ch * 4) * 4;

    float d[4][4][4];
    #pragma unroll
    for (int mi = 0; mi < 4; mi++)
        #pragma unroll
        for (int ni = 0; ni < 4; ni++)
            #pragma unroll
            for (int e = 0; e < 4; e++) d[mi][ni][e] = 0.f;

    auto issue = [&](int kt) {
        uint32_t As = smbase + (uint32_t)(kt % 3) * STW * 4;
        uint32_t Bs = As + HSW * 4;
        int kh = kt * 32;
        cp16(As + doff,           Xp + kh);
        cp16(As + doff + 64*SW*4, Xp + kh + (size_t)64 * EMB);
        cp16(Bs + doff,           Wp + kh);
        cp16(Bs + doff + 64*SW*4, Wp + kh + (size_t)64 * EMB);
        asm volatile("cp.async.commit_group;" ::: "memory");
    };

    issue(0);
    issue(1);

    for (int kt = 0; kt < 16; kt++) {
        if (kt < 15) asm volatile("cp.async.wait_group 1;" ::: "memory");
        else         asm volatile("cp.async.wait_group 0;" ::: "memory");
        __syncthreads();

        const uint32_t* As = sm + (kt % 3) * STW;
        const uint32_t* Bs = As + HSW;
        #pragma unroll
        for (int ks = 0; ks < 2; ks++) {
            const int kcol = 8*ks + 2*lc;
            uint2 a_lo[4], a_hi[4], bf[4];
            #pragma unroll
            for (int mi = 0; mi < 4; mi++) {
                a_lo[mi] = *(const uint2*)&As[(wm + mi*16 + lr)     * SW + kcol];
                a_hi[mi] = *(const uint2*)&As[(wm + mi*16 + 8 + lr) * SW + kcol];
            }
            #pragma unroll
            for (int ni = 0; ni < 4; ni++)
                bf[ni] = *(const uint2*)&Bs[(wn + ni*8 + lr) * SW + kcol];
            #pragma unroll
            for (int mi = 0; mi < 4; mi++)
                #pragma unroll
                for (int ni = 0; ni < 4; ni++)
                    mma_f16(d[mi][ni], a_lo[mi].x, a_hi[mi].x, a_lo[mi].y, a_hi[mi].y,
                            bf[ni].x, bf[ni].y);
        }
        // write buffer (kt+2)%3 == (kt-1)%3: readers passed this iteration's sync.
        if (kt < 14) issue(kt + 2);
    }

    #pragma unroll
    for (int mi = 0; mi < 4; mi++) {
        int row0 = m0 + wm + mi*16 + lr;
        #pragma unroll
        for (int ni = 0; ni < 4; ni++) {
            int col = n0 + wn + ni*8 + 2*lc;
            float v0 = d[mi][ni][0], v1 = d[mi][ni][1];
            epi_pair(v0, v1, row0, col, bias, mode);
            *(float2*)&C[(size_t)row0 * EMB + col] = make_float2(v0, v1);
            float v2 = d[mi][ni][2], v3 = d[mi][ni][3];
            epi_pair(v2, v3, row0 + 8, col, bias, mode);
            *(float2*)&C[(size_t)(row0 + 8) * EMB + col] = make_float2(v2, v3);
        }
    }
}

__global__ void __launch_bounds__(256) proj_kernel(
    const float* __restrict__ bq, const float* __restrict__ bk,
    const float* __restrict__ bv, const float* __restrict__ bg)
{
    int job = blockIdx.z;
    const __half* X; const __half* W; const float* B; float* O; int mode;
    if      (job == 0) { X = g_CXq; W = g_CW + 0*EMB*EMB; B = bq; O = g_Q; mode = 1; }
    else if (job == 1) { X = g_CXk; W = g_CW + 1*EMB*EMB; B = bk; O = g_K; mode = 2; }
    else if (job == 2) { X = g_CXv; W = g_CW + 2*EMB*EMB; B = bv; O = g_V; mode = 0; }
    else               { X = g_CXq; W = g_CW + 3*EMB*EMB; B = bg; O = g_G; mode = 3; }
    gemm_tc(X, W, B, O, mode);
}

__global__ void __launch_bounds__(256) out_kernel(
    const float* __restrict__ bo, float* __restrict__ out)
{
    gemm_tc(g_CX2, g_CW + 4*EMB*EMB, bo, out, 0);
}

// ================= chunkwise retention =================
// R1: per-chunk A = (K * gamma^(C-j))^T V   [64 x 64]
__global__ void __launch_bounds__(256) chunk_kv_kernel()
{
    __shared__ float Ks[CHUNK * HDIM];
    __shared__ float Vs[CHUNK * HDIM];

    const int tid = threadIdx.x;
    const int tx  = tid & 15;
    const int ty  = tid >> 4;
    const int c   = blockIdx.x;
    const int h   = blockIdx.y;
    const int b   = blockIdx.z;
    const int rowbase = b * SEQ + c * CHUNK;
    const int coff    = h * HDIM;

    const float lg = g_hc[h*4 + 1];

    for (int f = tid; f < CHUNK * 16; f += 256) {
        int s  = f >> 4;
        int d4 = f & 15;
        size_t gidx = (size_t)(rowbase + s) * EMB + coff + d4*4;
        float sc = expf(lg * (float)(CHUNK - s));
        float4 kv = *(const float4*)&g_K[gidx];
        kv.x *= sc; kv.y *= sc; kv.z *= sc; kv.w *= sc;
        *(float4*)&Ks[s*HDIM + d4*4] = kv;
        *(float4*)&Vs[s*HDIM + d4*4] = *(const float4*)&g_V[gidx];
    }
    __syncthreads();

    float acc[4][4];
    #pragma unroll
    for (int i = 0; i < 4; i++)
        #pragma unroll
        for (int j = 0; j < 4; j++) acc[i][j] = 0.f;

    #pragma unroll 8
    for (int s = 0; s < CHUNK; s++) {
        float4 a = *(const float4*)&Ks[s*HDIM + ty*4];
        float4 bb = *(const float4*)&Vs[s*HDIM + tx*4];
        float av[4] = {a.x, a.y, a.z, a.w};
        float bv[4] = {bb.x, bb.y, bb.z, bb.w};
        #pragma unroll
        for (int i = 0; i < 4; i++)
            #pragma unroll
            for (int j = 0; j < 4; j++)
                acc[i][j] = fmaf(av[i], bv[j], acc[i][j]);
    }

    float* Ap = g_A + (size_t)(((b*HEADS + h)*NCH + c) * HDIM * HDIM);
    #pragma unroll
    for (int i = 0; i < 4; i++)
        *(float4*)&Ap[(ty*4+i)*HDIM + tx*4] =
            make_float4(acc[i][0], acc[i][1], acc[i][2], acc[i][3]);
}

// R2: blocked parallel scan over chunks.
__global__ void __launch_bounds__(256) state_scan_kernel()
{
    __shared__ float Ts[4][64];

    const int tid  = threadIdx.x;
    const int e_lo = tid & 63;
    const int tq   = tid >> 6;
    const int bh   = blockIdx.x;
    const int eseg = blockIdx.y;
    const int e    = eseg * 64 + e_lo;
    const int h    = bh & (HEADS - 1);

    const float gc  = g_hc[h*4 + 2];
    const float gc8 = g_hc[h*4 + 3];

    const size_t base = (size_t)bh * NCH * HDIM * HDIM + e;
    const size_t toff = (size_t)(tq * 8) * HDIM * HDIM;

    float a[8];
    #pragma unroll
    for (int i = 0; i < 8; i++)
        a[i] = g_A[base + toff + (size_t)i * HDIM * HDIM];

    float p[8];
    float s = 0.f;
    #pragma unroll
    for (int i = 0; i < 8; i++) { p[i] = s; s = gc * s + a[i]; }
    Ts[tq][e_lo] = s;
    __syncthreads();

    float cr = 0.f;
    if (tq >= 1) cr = Ts[0][e_lo];
    if (tq >= 2) cr = gc8 * cr + Ts[1][e_lo];
    if (tq >= 3) cr = gc8 * cr + Ts[2][e_lo];

    float gpow = 1.f;
    #pragma unroll
    for (int i = 0; i < 8; i++) {
        g_S[base + toff + (size_t)i * HDIM * HDIM] = fmaf(gpow, cr, p[i]);
        gpow *= gc;
    }
}

// R3: intra-chunk + cross term via state, fused GroupNorm*gate.
// Epilogue writes fp16, k-permuted output directly to g_CX2.
__global__ void __launch_bounds__(256) retention_kernel()
{
    __shared__ float QsT[HDIM * CHUNK];
    __shared__ float KsT[HDIM * CHUNK];
    __shared__ float Vs [CHUNK * HDIM];
    __shared__ float Ss [HDIM * HDIM];

    const int tid = threadIdx.x;
    const int tx  = tid & 15;
    const int ty  = tid >> 4;
    const int c   = blockIdx.x;
    const int h   = blockIdx.y;
    const int b   = blockIdx.z;
    const int rowbase = b * SEQ + c * CHUNK;
    const int coff    = h * HDIM;

    const float gamma = g_hc[h*4 + 0];
    const float lg    = g_hc[h*4 + 1];
    float gi[4], gjv[4];
    gi[0]  = 1.f; gi[1] = gamma; gi[2] = gamma*gamma; gi[3] = gi[2]*gamma;
    float ginv = 1.f / gamma;
    gjv[0] = 1.f; gjv[1] = ginv; gjv[2] = ginv*ginv;  gjv[3] = gjv[2]*ginv;

    const float* Sp = g_S + (size_t)(((b*HEADS + h)*NCH + c) * HDIM * HDIM);
    for (int f = tid; f < CHUNK * 16; f += 256) {
        int s  = f & 63;
        int d4 = f >> 6;
        size_t gidx = (size_t)(rowbase + s) * EMB + coff + d4*4;
        float4 qv = *(const float4*)&g_Q[gidx];
        QsT[(d4*4+0)*CHUNK + s] = qv.x;
        QsT[(d4*4+1)*CHUNK + s] = qv.y;
        QsT[(d4*4+2)*CHUNK + s] = qv.z;
        QsT[(d4*4+3)*CHUNK + s] = qv.w;
        float4 kv = *(const float4*)&g_K[gidx];
        KsT[(d4*4+0)*CHUNK + s] = kv.x;
        KsT[(d4*4+1)*CHUNK + s] = kv.y;
        KsT[(d4*4+2)*CHUNK + s] = kv.z;
        KsT[(d4*4+3)*CHUNK + s] = kv.w;
        *(float4*)&Vs[s*HDIM + d4*4] = *(const float4*)&g_V[gidx];
        *(float4*)&Ss[f*4] = *(const float4*)&Sp[f*4];
    }
    __syncthreads();

    float sacc[4][4];
    #pragma unroll
    for (int i = 0; i < 4; i++)
        #pragma unroll
        for (int j = 0; j < 4; j++) sacc[i][j] = 0.f;
    #pragma unroll 8
    for (int d = 0; d < HDIM; d++) {
        float4 a  = *(const float4*)&QsT[d*CHUNK + ty*4];
        float4 bb = *(const float4*)&KsT[d*CHUNK + tx*4];
        float av[4] = {a.x, a.y, a.z, a.w};
        float bv[4] = {bb.x, bb.y, bb.z, bb.w};
        #pragma unroll
        for (int i = 0; i < 4; i++)
            #pragma unroll
            for (int j = 0; j < 4; j++)
                sacc[i][j] = fmaf(av[i], bv[j], sacc[i][j]);
    }
    {
        float d0 = expf(lg * (float)(ty*4 - tx*4));
        #pragma unroll
        for (int i = 0; i < 4; i++) {
            int n = ty*4 + i;
            #pragma unroll
            for (int j = 0; j < 4; j++) {
                int s = tx*4 + j;
                sacc[i][j] = (s <= n) ? sacc[i][j] * d0 * gi[i] * gjv[j] : 0.f;
            }
        }
    }
    __syncthreads();
    #pragma unroll
    for (int j = 0; j < 4; j++)
        *(float4*)&KsT[(tx*4+j)*CHUNK + ty*4] =
            make_float4(sacc[0][j], sacc[1][j], sacc[2][j], sacc[3][j]);
    __syncthreads();

    float oacc[4][4];
    #pragma unroll
    for (int i = 0; i < 4; i++)
        #pragma unroll
        for (int j = 0; j < 4; j++) oacc[i][j] = 0.f;
    #pragma unroll 8
    for (int s = 0; s < CHUNK; s++) {
        float4 a  = *(const float4*)&KsT[s*CHUNK + ty*4];
        float4 bb = *(const float4*)&Vs[s*HDIM + tx*4];
        float av[4] = {a.x, a.y, a.z, a.w};
        float bv[4] = {bb.x, bb.y, bb.z, bb.w};
        #pragma unroll
        for (int i = 0; i < 4; i++)
            #pragma unroll
            for (int j = 0; j < 4; j++)
                oacc[i][j] = fmaf(av[i], bv[j], oacc[i][j]);
    }

    {
        float cacc[4][4];
        #pragma unroll
        for (int i = 0; i < 4; i++)
            #pragma unroll
            for (int j = 0; j < 4; j++) cacc[i][j] = 0.f;
        #pragma unroll 8
        for (int d = 0; d < HDIM; d++) {
            float4 a  = *(const float4*)&QsT[d*CHUNK + ty*4];
            float4 bb = *(const float4*)&Ss[d*HDIM + tx*4];
            float av[4] = {a.x, a.y, a.z, a.w};
            float bv[4] = {bb.x, bb.y, bb.z, bb.w};
            #pragma unroll
            for (int i = 0; i < 4; i++)
                #pragma unroll
                for (int j = 0; j < 4; j++)
                    cacc[i][j] = fmaf(av[i], bv[j], cacc[i][j]);
        }
        #pragma unroll
        for (int i = 0; i < 4; i++) {
            float gq = expf(lg * (float)(ty*4 + i));
            #pragma unroll
            for (int j = 0; j < 4; j++)
                oacc[i][j] = fmaf(gq, cacc[i][j], oacc[i][j]);
        }
    }

    __syncthreads();
    #pragma unroll
    for (int i = 0; i < 4; i++)
        *(float4*)&KsT[(ty*4+i)*HDIM + tx*4] =
            make_float4(oacc[i][0], oacc[i][1], oacc[i][2], oacc[i][3]);
    __syncthreads();

    const int r = tid >> 2;
    const int p = tid & 3;
    float vals[16];
    float lsum = 0.f;
    #pragma unroll
    for (int j = 0; j < 16; j++) {
        vals[j] = KsT[r*HDIM + p*16 + j];
        lsum += vals[j];
    }
    lsum += __shfl_xor_sync(0xffffffffu, lsum, 1);
    lsum += __shfl_xor_sync(0xffffffffu, lsum, 2);
    float mean = lsum * (1.f / 64.f);
    float lsq = 0.f;
    #pragma unroll
    for (int j = 0; j < 16; j++) {
        float dd = vals[j] - mean;
        lsq += dd * dd;
    }
    lsq += __shfl_xor_sync(0xffffffffu, lsq, 1);
    lsq += __shfl_xor_sync(0xffffffffu, lsq, 2);
    float rstd = rsqrtf(lsq * (1.f / 64.f) + 1e-6f);

    const int n = c * CHUNK + r;
    const size_t rowoff = (size_t)(b * SEQ + n) * EMB;
    #pragma unroll
    for (int j = 0; j < 16; j++) {
        int col = coff + p*16 + j;
        float gte = g_G[rowoff + col];
        float v = (vals[j] - mean) * rstd * gte;
        // permuted fp16 store (same mapping as cvt_rows_h4)
        int ktile = col >> 5;
        int k5    = col & 31;
        int g16   = k5 >> 4;
        int kk    = k5 & 15;
        int jw    = kk >> 1;
        int e     = kk & 1;
        int permw = g16*8 + ((jw < 4) ? 2*jw : 2*(jw-4)+1);
        g_CX2[rowoff + ktile*32 + permw*2 + e] = __float2half_rn(v);
    }
}

// ---------------- launch ----------------
extern "C" void kernel_launch(void* const* d_in, const int* in_sizes, int n_in,
                              void* d_out, int out_size)
{
    const float* query = (const float*)d_in[0];
    const float* kk    = (const float*)d_in[1];
    const float* vv    = (const float*)d_in[2];
    const float* Wq    = (const float*)d_in[3];
    const float* bq    = (const float*)d_in[4];
    const float* Wk    = (const float*)d_in[5];
    const float* bk    = (const float*)d_in[6];
    const float* Wv    = (const float*)d_in[7];
    const float* bv    = (const float*)d_in[8];
    const float* Wg    = (const float*)d_in[9];
    const float* bg    = (const float*)d_in[10];
    const float* Wo    = (const float*)d_in[11];
    const float* bo    = (const float*)d_in[12];
    float* out = (float*)d_out;

    const int SMEM_GEMM = 3 * 2 * 128 * 24 * 4;   // 73728 B -> 2 CTAs/SM
    cudaFuncSetAttribute(proj_kernel, cudaFuncAttributeMaxDynamicSharedMemorySize, SMEM_GEMM);
    cudaFuncSetAttribute(out_kernel,  cudaFuncAttributeMaxDynamicSharedMemorySize, SMEM_GEMM);

    dim3 cg(MTOT * 64 / 256, 8);          // 4 words/thread; job 0 also does setup
    cvt_inputs_kernel<<<cg, 256>>>(query, kk, vv, Wq, Wk, Wv, Wg, Wo);

    dim3 pg(4, 32, 4);
    proj_kernel<<<pg, 256, SMEM_GEMM>>>(bq, bk, bv, bg);

    dim3 ag(NCH, HEADS, BATCH);
    chunk_kv_kernel<<<ag, 256>>>();

    dim3 sg(NBH, 64);
    state_scan_kernel<<<sg, 256>>>();

    dim3 rg(NCH, HEADS, BATCH);
    retention_kernel<<<rg, 256>>>();

    dim3 og(4, 32, 1);
    out_kernel<<<og, 256, SMEM_GEMM>>>(bo, out);
}